// round 17
// baseline (speedup 1.0000x reference)
#include <cuda_runtime.h>
#include <utility>

namespace tp {

constexpr int LMAX = 4;
constexpr int NM   = 25;    // (L+1)^2
constexpr int NB   = 128;
constexpr int NC   = 128;   // scalar f32 columns per (b, m) row
constexpr int MAXNNZ = 8192;

constexpr int iabs(int v) { return v < 0 ? -v : v; }

struct Pat {
  int nnz;
  short seg[MAXNNZ];
  short m1[MAXNNZ];
  short m2[MAXNNZ];
};

// Replicates reference _build_cg_pattern() INCLUDING the sort.
constexpr Pat build_pat() {
  Pat p{};
  int n = 0;
  for (int lo = 0; lo <= LMAX; ++lo)
    for (int mo = -lo; mo <= lo; ++mo)
      for (int l1 = 0; l1 <= LMAX; ++l1)
        for (int u1 = -l1; u1 <= l1; ++u1)
          for (int l2 = 0; l2 <= LMAX; ++l2) {
            if (l2 < iabs(lo - l1) || l2 > lo + l1) continue;
            for (int u2 = -l2; u2 <= l2; ++u2) {
              if (iabs(u1 + u2) == iabs(mo) || iabs(u1 - u2) == iabs(mo)) {
                p.seg[n] = (short)(lo * (lo + 1) + mo);
                p.m1 [n] = (short)(l1 * (l1 + 1) + u1);
                p.m2 [n] = (short)(l2 * (l2 + 1) + u2);
                ++n;
              }
            }
          }
  p.nnz = n;
  return p;
}

constexpr Pat PAT = build_pat();
constexpr int NNZ = PAT.nnz;
static_assert(NNZ > 0 && NNZ < MAXNNZ, "nnz bounds");

constexpr int NG    = 4;   // segment groups; ONE group per CTA
constexpr int NT    = 512; // 16 warps = 4 b x 128 scalar columns
constexpr int CHUNK = 8;   // cg values per batch (2x LDS.128)

// Flattened pair-major execution plan (counting-sort pair order per group).
struct Plan {
  int e[NG + 1];
  int mlo[NG], mhi[NG];
  unsigned u1[NG], u2[NG];
  int fb[NG + 1];
  short fseg[MAXNNZ];
  short fm1[MAXNNZ], fm2[MAXNNZ];
  short ffirst[MAXNNZ];
  short fcgi[MAXNNZ];
};

constexpr Plan build_plan() {
  Plan s{};
  int segstart[NM + 1] = {};
  {
    int pos = 0;
    for (int m = 0; m <= NM; ++m) {
      while (pos < NNZ && PAT.seg[pos] < m) ++pos;
      segstart[m] = pos;
    }
  }
  s.e[0] = 0; s.e[NG] = NNZ;
  for (int g = 1; g < NG; ++g) {
    int target = (NNZ * g) / NG;
    int best = 0, bd = 1 << 30;
    for (int m = 0; m <= NM; ++m) {
      int d = segstart[m] - target; if (d < 0) d = -d;
      if (d < bd) { bd = d; best = segstart[m]; }
    }
    s.e[g] = best;
  }
  int nf = 0;
  for (int g = 0; g < NG; ++g) {
    const int e0 = s.e[g], e1 = s.e[g + 1];
    s.mlo[g] = (e0 < NNZ) ? (int)PAT.seg[e0] : NM;
    s.mhi[g] = (e1 < NNZ) ? (int)PAT.seg[e1] : NM;
    s.fb[g] = nf;
    unsigned u1 = 0, u2 = 0;
    int cnt[NM * NM] = {};
    for (int j = e0; j < e1; ++j) {
      u1 |= 1u << PAT.m1[j];
      u2 |= 1u << PAT.m2[j];
      cnt[PAT.m1[j] * NM + PAT.m2[j]]++;
    }
    int off[NM * NM] = {};
    int base[NM * NM] = {};
    for (int pid = 0; pid < NM * NM; ++pid) {
      if (cnt[pid]) { off[pid] = nf; base[pid] = nf; nf += cnt[pid]; }
    }
    for (int j = e0; j < e1; ++j) {
      int pid = PAT.m1[j] * NM + PAT.m2[j];
      int pos = off[pid]++;
      s.fseg[pos]  = PAT.seg[j];
      s.fm1[pos]   = PAT.m1[j];
      s.fm2[pos]   = PAT.m2[j];
      s.fcgi[pos]  = (short)j;
      s.ffirst[pos] = (short)(pos == base[pid]);
    }
    s.u1[g] = u1; s.u2[g] = u2;
  }
  s.fb[NG] = nf;
  return s;
}

constexpr Plan PLAN = build_plan();

// Packed cg layout: plan order, group bases padded to CHUNK -> 16B-aligned
// float4 batches, tail over-read safe.
struct Pack {
  int delta[NG];
  short idx[MAXNNZ + CHUNK * NG];
  int total;
};

constexpr Pack build_pack() {
  Pack k{};
  int p = 0;
  for (int g = 0; g < NG; ++g) {
    k.delta[g] = p - PLAN.fb[g];
    const int len = PLAN.fb[g + 1] - PLAN.fb[g];
    for (int i = 0; i < len; ++i) k.idx[p + i] = PLAN.fcgi[PLAN.fb[g] + i];
    p += (len + CHUNK - 1) / CHUNK * CHUNK;
  }
  k.total = p;
  return k;
}

constexpr Pack PK = build_pack();
constexpr int NF2 = PK.total;

struct IdxArr { short v[MAXNNZ + CHUNK * NG]; };
constexpr IdxArr make_idx() {
  IdxArr a{};
  for (int i = 0; i < MAXNNZ + CHUNK * NG; ++i) a.v[i] = PK.idx[i];
  return a;
}
__device__ const IdxArr d_pidx = make_idx();

// All PLAN/PK reads appear ONLY in template-argument position.
// NO inline asm anywhere in the hot path: plain float math, ptxas owns the
// schedule, FFMA contraction is native, no 64-bit register-pair banking.

template<int FIRST, int A, int B2, int SEGR>
__device__ __forceinline__ void step(float* __restrict__ acc,
                                     const float* __restrict__ x1r,
                                     const float* __restrict__ x2r,
                                     float& p, float cgv) {
  if constexpr (FIRST) p = x1r[A] * x2r[B2];
  acc[SEGR] += cgv * p;          // contracts to FFMA
}

template<int PPOS, int N>
__device__ __forceinline__ void load_cg(float* __restrict__ buf,
                                        const float* __restrict__ scg) {
  const float4* v = reinterpret_cast<const float4*>(scg + PPOS);
#pragma unroll
  for (int i = 0; i < (N + 3) / 4; ++i) {
    float4 t = v[i];
    buf[4 * i + 0] = t.x; buf[4 * i + 1] = t.y;
    buf[4 * i + 2] = t.z; buf[4 * i + 3] = t.w;
  }
}

template<int MLO, int POS, int DELTA, int... K>
__device__ __forceinline__ void run_chunk(float* __restrict__ acc,
                                          const float* __restrict__ x1r,
                                          const float* __restrict__ x2r,
                                          const float* __restrict__ scg, float& p,
                                          std::integer_sequence<int, K...>) {
  float cgv[CHUNK];
  load_cg<POS + DELTA, sizeof...(K)>(cgv, scg);
  ( step<PLAN.ffirst[POS + K], PLAN.fm1[POS + K], PLAN.fm2[POS + K],
         PLAN.fseg[POS + K] - MLO>(acc, x1r, x2r, p, cgv[K]), ... );
}

template<int MLO, int FB, int FE, int DELTA, int... C>
__device__ __forceinline__ void run_chunks(float* __restrict__ acc,
                                           const float* __restrict__ x1r,
                                           const float* __restrict__ x2r,
                                           const float* __restrict__ scg,
                                           std::integer_sequence<int, C...>) {
  float p = 0.f;
  ( run_chunk<MLO, FB + C * CHUNK, DELTA>(
        acc, x1r, x2r, scg, p,
        std::make_integer_sequence<int,
            ((FE - (FB + C * CHUNK)) < CHUNK ? (FE - (FB + C * CHUNK)) : CHUNK)>{}),
    ... );
}

template<unsigned MASK, int M>
__device__ __forceinline__ void load1(float* __restrict__ r,
                                      const float* __restrict__ src, int c) {
  if constexpr ((MASK >> M) & 1u) r[M] = src[M * NC + c];
}
template<unsigned MASK, int... M>
__device__ __forceinline__ void loadm(float* __restrict__ r,
                                      const float* __restrict__ src, int c,
                                      std::integer_sequence<int, M...>) {
  ( load1<MASK, M>(r, src, c), ... );
}

template<int MLO, int... S>
__device__ __forceinline__ void storem(float* __restrict__ outp,
                                       const float* __restrict__ acc, int c,
                                       std::integer_sequence<int, S...>) {
  ( (outp[(MLO + S) * NC + c] = acc[S]), ... );
}

template<int MLO, int MHI, int FB, int FE, int DELTA, unsigned U1, unsigned U2>
__device__ __forceinline__ void rg(const float* __restrict__ x1p,
                                   const float* __restrict__ x2p,
                                   float* __restrict__ outp,
                                   const float* __restrict__ scg, int c) {
  float x1r[NM], x2r[NM];
  loadm<U1>(x1r, x1p, c, std::make_integer_sequence<int, NM>{});
  loadm<U2>(x2r, x2p, c, std::make_integer_sequence<int, NM>{});
  float acc[MHI - MLO] = {};
  run_chunks<MLO, FB, FE, DELTA>(
      acc, x1r, x2r, scg,
      std::make_integer_sequence<int, (FE - FB + CHUNK - 1) / CHUNK>{});
  storem<MLO>(outp, acc, c, std::make_integer_sequence<int, MHI - MLO>{});
}

template<int G>
__device__ __forceinline__ void rung(const float* __restrict__ x1p,
                                     const float* __restrict__ x2p,
                                     float* __restrict__ outp,
                                     const float* __restrict__ scg, int c) {
  rg<PLAN.mlo[G], PLAN.mhi[G], PLAN.fb[G], PLAN.fb[G + 1], PK.delta[G],
     PLAN.u1[G], PLAN.u2[G]>(x1p, x2p, outp, scg, c);
}

// CTA = (group, b-quad): 16 warps = 4 b x 128 scalar columns, all executing
// the SAME group region (R11's shared-I-stream property). Grid = 4 groups x
// 32 quads = 128 CTAs -> one uniform wave, 1 CTA/SM.
__global__ void __launch_bounds__(NT, 1)
tp_kernel(const float* __restrict__ x1, const float* __restrict__ x2,
          const float* __restrict__ cg, float* __restrict__ out) {
  __shared__ __align__(16) float scg[NF2];   // packed cg (plan order)
  const int tid = threadIdx.x;
  for (int i = tid; i < NF2; i += NT) scg[i] = __ldg(cg + d_pidx.v[i]);
  __syncthreads();

  const int g    = blockIdx.x >> 5;        // group: uniform per CTA
  const int quad = blockIdx.x & 31;        // b-quad
  const int b    = quad * 4 + (tid >> 7);  // 4 b per CTA (128 threads each)
  const int c    = tid & 127;              // scalar column index

  const float* x1p = x1  + b * (NM * NC);
  const float* x2p = x2  + b * (NM * NC);
  float*       op  = out + b * (NM * NC);

  switch (g) {
    case 0: rung<0>(x1p, x2p, op, scg, c); break;
    case 1: rung<1>(x1p, x2p, op, scg, c); break;
    case 2: rung<2>(x1p, x2p, op, scg, c); break;
    case 3: rung<3>(x1p, x2p, op, scg, c); break;
  }
}

// ---- generic fallback (only if runtime nnz != compile-time NNZ) ----
__global__ void tp_generic(const float* __restrict__ x1, const float* __restrict__ x2,
                           const float* __restrict__ cg,
                           const int* __restrict__ M1, const int* __restrict__ M2,
                           const int* __restrict__ seg, int nnz,
                           float* __restrict__ out) {
  const int b = blockIdx.x;
  const int c = threadIdx.x;
  const float* x1b = x1 + b * NM * NC;
  const float* x2b = x2 + b * NM * NC;
  float acc = 0.f;
  int cur = seg[0];
  for (int i = 0; i < nnz; ++i) {
    int s = seg[i];
    if (s != cur) { out[(b * NM + cur) * NC + c] = acc; acc = 0.f; cur = s; }
    acc += cg[i] * x1b[M1[i] * NC + c] * x2b[M2[i] * NC + c];
  }
  out[(b * NM + cur) * NC + c] = acc;
}

}  // namespace tp

extern "C" void kernel_launch(void* const* d_in, const int* in_sizes, int n_in,
                              void* d_out, int out_size) {
  const float* x1 = (const float*)d_in[0];
  const float* x2 = (const float*)d_in[1];
  const float* cg = (const float*)d_in[2];
  const int*   M1 = (const int*)  d_in[3];
  const int*   M2 = (const int*)  d_in[4];
  const int*   sg = (const int*)  d_in[5];
  float* out = (float*)d_out;

  if (in_sizes[2] == tp::NNZ) {
    tp::tp_kernel<<<tp::NG * 32, tp::NT>>>(x1, x2, cg, out);
  } else {
    cudaMemsetAsync(d_out, 0, (size_t)out_size * sizeof(float));
    tp::tp_generic<<<tp::NB, tp::NC>>>(x1, x2, cg, M1, M2, sg, in_sizes[2], out);
  }
}